// round 3
// baseline (speedup 1.0000x reference)
#include <cuda_runtime.h>
#include <cstdint>
#include <cstddef>

#define KCODES 8192
#define DDIM   256
#define NROWS  32768
#define GAMMA_F 0.99f
#define EPS_F   1e-5f

// ---- argmin tiling ----
#define TM 128                     // rows per tile
#define TN 128                     // codes per ktile
#define KSPLIT 2048                // codes per work tile
#define NTILE_R (NROWS / TM)       // 256
#define NTILE_K (KCODES / KSPLIT)  // 4
#define NTILES  (NTILE_R * NTILE_K)
#define LD 130                     // padded row length (floats), even -> 8B aligned pairs
#define ZS_FLOATS  (DDIM * LD)     // 33280
#define WCH_FLOATS (32 * LD)       // 4160 per chunk array
#define ARG_SMEM ((ZS_FLOATS + 4 * WCH_FLOATS) * 4)   // 199,680 B

// ---------------- scratch ----------------
__device__ unsigned long long g_best[NROWS];
__device__ float g_wnorm[KCODES];
__device__ float g_cnt[KCODES];
__device__ float g_commit;
__device__ float g_nsum;
__device__ unsigned int g_ctr;

// ---------------- kernel 1: init ----------------
__global__ void k_init(const float* __restrict__ W, const float* __restrict__ mt,
                       float* __restrict__ out_mt) {
    int i = blockIdx.x * blockDim.x + threadIdx.x;
    out_mt[i] = GAMMA_F * mt[i];
    if (i < KCODES) {
        const float4* w = (const float4*)(W + (size_t)i * DDIM);
        float s = 0.f;
        #pragma unroll 8
        for (int q = 0; q < DDIM / 4; ++q) {
            float4 v = w[q];
            s += v.x * v.x + v.y * v.y + v.z * v.z + v.w * v.w;
        }
        g_wnorm[i] = 0.5f * s;
        g_cnt[i]   = 0.f;
    }
    if (i < NROWS) g_best[i] = 0ull;
    if (i == 0) { g_commit = 0.f; g_nsum = 0.f; g_ctr = 0u; }
}

// ---------------- kernel 2: fused score-GEMM + argmax (packed f32x2) ----------------
__device__ __forceinline__ unsigned long long fkey(float s, int code) {
    unsigned u = __float_as_uint(s);
    u = (u & 0x80000000u) ? ~u : (u | 0x80000000u);
    return ((unsigned long long)u << 32) | (unsigned)(KCODES - 1 - code);
}
__device__ __forceinline__ float2 unpk(unsigned long long v) {
    float2 r;
    r.x = __uint_as_float((unsigned)(v & 0xffffffffu));
    r.y = __uint_as_float((unsigned)(v >> 32));
    return r;
}
__device__ __forceinline__ unsigned long long umax64(unsigned long long a, unsigned long long b) {
    return a > b ? a : b;
}

__global__ void __launch_bounds__(256, 1)
k_argmin(const float* __restrict__ ze, const float* __restrict__ W) {
    extern __shared__ float sm[];
    float* Zs   = sm;                 // [256 d][LD rows] transposed Z tile
    float* Wbuf = sm + ZS_FLOATS;     // [2 buf][ Wn | Wx ] each [32 d][LD codes]
    __shared__ unsigned int s_tile;

    const int tid = threadIdx.x;
    const int tx  = tid & 15;    // code-pair group
    const int ty  = tid >> 4;    // row-pair group

    int pn[4], pq[4];            // W-chunk fill mapping: 4 float4/thread = [128 codes x 32 d]
    #pragma unroll
    for (int p = 0; p < 4; ++p) {
        int l = tid + 256 * p;
        pn[p] = l >> 3;
        pq[p] = (l & 7) * 4;
    }

    for (;;) {
        if (tid == 0) s_tile = atomicAdd(&g_ctr, 1u);
        __syncthreads();
        unsigned tile = s_tile;
        if (tile >= NTILES) break;
        const int rowBase = (int)(tile >> 2) * TM;
        const int kt0     = (int)(tile & 3) * KSPLIT;

        // ---- fill transposed Z tile ----
        {
            const float4* zg = (const float4*)(ze + (size_t)rowBase * DDIM);
            #pragma unroll
            for (int p = 0; p < 32; ++p) {
                int l = tid + 256 * p;
                int m = l >> 6;        // row 0..127
                int q = l & 63;        // float4 index along d
                float4 v = zg[(size_t)m * 64 + q];
                float* d0 = &Zs[(4 * q) * LD + m];
                d0[0 * LD] = v.x; d0[1 * LD] = v.y;
                d0[2 * LD] = v.z; d0[3 * LD] = v.w;
            }
        }

        // ---- prefetch + store W chunk 0 into buffer 0 ----
        float4 pre[4];
        {
            const float* base = W + (size_t)kt0 * DDIM;
            #pragma unroll
            for (int p = 0; p < 4; ++p)
                pre[p] = *(const float4*)(base + (size_t)pn[p] * DDIM + pq[p]);
        }
        {
            float* Wn = Wbuf;
            float* Wx = Wbuf + WCH_FLOATS;
            #pragma unroll
            for (int p = 0; p < 4; ++p) {
                float v[4] = {pre[p].x, pre[p].y, pre[p].z, pre[p].w};
                #pragma unroll
                for (int e = 0; e < 4; ++e) {
                    Wn[(pq[p] + e) * LD + pn[p]]       = v[e];
                    Wx[(pq[p] + e) * LD + (pn[p] ^ 1)] = v[e];
                }
            }
        }
        __syncthreads();

        unsigned long long best0[4], best1[4];
        #pragma unroll
        for (int p = 0; p < 4; ++p) { best0[p] = 0ull; best1[p] = 0ull; }

        int buf = 0;
        for (int kt = 0; kt < KSPLIT / TN; ++kt) {          // 16 ktiles
            unsigned long long accd[4][4], accx[4][4];
            #pragma unroll
            for (int p = 0; p < 4; ++p)
                #pragma unroll
                for (int q = 0; q < 4; ++q) { accd[p][q] = 0ull; accx[p][q] = 0ull; }

            for (int c = 0; c < 8; ++c) {                   // D chunks of 32
                const int g = kt * 8 + c;
                const bool hn = (g + 1 < (KSPLIT / TN) * 8);
                if (hn) {
                    int ng = g + 1, nkt = ng >> 3, nc = ng & 7;
                    const float* base = W + (size_t)(kt0 + nkt * TN) * DDIM + nc * 32;
                    #pragma unroll
                    for (int p = 0; p < 4; ++p)
                        pre[p] = *(const float4*)(base + (size_t)pn[p] * DDIM + pq[p]);
                }

                const float* Wn = Wbuf + buf * 2 * WCH_FLOATS;
                const float* Wx = Wn + WCH_FLOATS;
                const int dc = c * 32;
                #pragma unroll 8
                for (int kc = 0; kc < 32; ++kc) {
                    unsigned long long a2[4], b2[4], bx[4];
                    #pragma unroll
                    for (int p = 0; p < 4; ++p)
                        a2[p] = *(const unsigned long long*)(Zs + (dc + kc) * LD + 2 * ty + 32 * p);
                    #pragma unroll
                    for (int q = 0; q < 4; ++q) {
                        b2[q] = *(const unsigned long long*)(Wn + kc * LD + 2 * tx + 32 * q);
                        bx[q] = *(const unsigned long long*)(Wx + kc * LD + 2 * tx + 32 * q);
                    }
                    #pragma unroll
                    for (int p = 0; p < 4; ++p)
                        #pragma unroll
                        for (int q = 0; q < 4; ++q) {
                            asm("fma.rn.f32x2 %0, %1, %2, %0;"
                                : "+l"(accd[p][q]) : "l"(a2[p]), "l"(b2[q]));
                            asm("fma.rn.f32x2 %0, %1, %2, %0;"
                                : "+l"(accx[p][q]) : "l"(a2[p]), "l"(bx[q]));
                        }
                }

                if (hn) {
                    float* Wn2 = Wbuf + (buf ^ 1) * 2 * WCH_FLOATS;
                    float* Wx2 = Wn2 + WCH_FLOATS;
                    #pragma unroll
                    for (int p = 0; p < 4; ++p) {
                        float v[4] = {pre[p].x, pre[p].y, pre[p].z, pre[p].w};
                        #pragma unroll
                        for (int e = 0; e < 4; ++e) {
                            Wn2[(pq[p] + e) * LD + pn[p]]       = v[e];
                            Wx2[(pq[p] + e) * LD + (pn[p] ^ 1)] = v[e];
                        }
                    }
                }
                __syncthreads();
                buf ^= 1;
            }

            // ---- per-ktile argmax merge (registers only) ----
            const int ktAbs = kt0 + kt * TN;
            float wa[4], wb[4];
            #pragma unroll
            for (int q = 0; q < 4; ++q) {
                int c0 = ktAbs + 2 * tx + 32 * q;
                wa[q] = __ldg(&g_wnorm[c0]);
                wb[q] = __ldg(&g_wnorm[c0 + 1]);
            }
            #pragma unroll
            for (int p = 0; p < 4; ++p) {
                unsigned long long k0 = best0[p], k1 = best1[p];
                #pragma unroll
                for (int q = 0; q < 4; ++q) {
                    int c0 = ktAbs + 2 * tx + 32 * q;
                    float2 dd = unpk(accd[p][q]);   // {r0*c0, r1*c1}
                    float2 xx = unpk(accx[p][q]);   // {r0*c1, r1*c0}
                    k0 = umax64(k0, fkey(dd.x - wa[q], c0));
                    k0 = umax64(k0, fkey(xx.x - wb[q], c0 + 1));
                    k1 = umax64(k1, fkey(xx.y - wa[q], c0));
                    k1 = umax64(k1, fkey(dd.y - wb[q], c0 + 1));
                }
                best0[p] = k0; best1[p] = k1;
            }
        }

        // ---- tile-end: reduce across the 16 tx lanes, publish via atomicMax ----
        #pragma unroll
        for (int p = 0; p < 4; ++p) {
            unsigned long long k0 = best0[p], k1 = best1[p];
            #pragma unroll
            for (int off = 1; off < 16; off <<= 1) {
                k0 = umax64(k0, __shfl_xor_sync(0xffffffffu, k0, off));
                k1 = umax64(k1, __shfl_xor_sync(0xffffffffu, k1, off));
            }
            if (tx == 0) {
                int r = rowBase + 2 * ty + 32 * p;
                atomicMax(&g_best[r],     k0);
                atomicMax(&g_best[r + 1], k1);
            }
        }
    }
}

// ---------------- kernel 3: gather/scatter ----------------
__global__ void k_scatter(const float* __restrict__ ze, const float* __restrict__ W,
                          float* __restrict__ out_zq, float* __restrict__ out_idx,
                          float* __restrict__ out_mt) {
    const int tid  = threadIdx.x;
    const int row  = blockIdx.x * 4 + (tid >> 6);
    const int lane = tid & 63;
    const int idx  = KCODES - 1 - (int)(g_best[row] & 0xffffffffu);

    const float4 z = *(const float4*)(ze + (size_t)row * DDIM + lane * 4);
    const float4 w = *(const float4*)(W  + (size_t)idx * DDIM + lane * 4);

    float4 q;   // straight-through: ze + (zq - ze)
    q.x = z.x + (w.x - z.x);
    q.y = z.y + (w.y - z.y);
    q.z = z.z + (w.z - z.z);
    q.w = z.w + (w.w - z.w);
    *(float4*)(out_zq + (size_t)row * DDIM + lane * 4) = q;

    float dx = w.x - z.x, dy = w.y - z.y, dz = w.z - z.z, dw = w.w - z.w;
    float csum = dx * dx + dy * dy + dz * dz + dw * dw;

    const float s = 1.0f - GAMMA_F;
    float* mptr = out_mt + (size_t)idx * DDIM + lane * 4;
    atomicAdd(mptr + 0, s * z.x);
    atomicAdd(mptr + 1, s * z.y);
    atomicAdd(mptr + 2, s * z.z);
    atomicAdd(mptr + 3, s * z.w);

    if (lane == 0) {
        atomicAdd(&g_cnt[idx], 1.0f);
        out_idx[row] = (float)idx;
    }

    __shared__ float red[8];
    #pragma unroll
    for (int off = 16; off > 0; off >>= 1)
        csum += __shfl_down_sync(0xffffffffu, csum, off);
    if ((tid & 31) == 0) red[tid >> 5] = csum;
    __syncthreads();
    if (tid < 8) {
        float v = red[tid];
        #pragma unroll
        for (int off = 4; off > 0; off >>= 1)
            v += __shfl_down_sync(0xffu, v, off);
        if (tid == 0) atomicAdd(&g_commit, v);
    }
}

// ---------------- kernel 4: Nt_new + n ----------------
__global__ void k_fin_nt(const float* __restrict__ Nt, float* __restrict__ out_Nt) {
    int k = blockIdx.x * 256 + threadIdx.x;
    float v = GAMMA_F * Nt[k] + (1.0f - GAMMA_F) * g_cnt[k];
    out_Nt[k] = v;
    __shared__ float red[8];
    float s = v;
    #pragma unroll
    for (int off = 16; off > 0; off >>= 1)
        s += __shfl_down_sync(0xffffffffu, s, off);
    if ((threadIdx.x & 31) == 0) red[threadIdx.x >> 5] = s;
    __syncthreads();
    if (threadIdx.x < 8) {
        float t = red[threadIdx.x];
        #pragma unroll
        for (int off = 4; off > 0; off >>= 1)
            t += __shfl_down_sync(0xffu, t, off);
        if (threadIdx.x == 0) atomicAdd(&g_nsum, t);
    }
}

// ---------------- kernel 5: embedW_new + commit ----------------
__global__ void k_fin_w(const float* __restrict__ out_Nt,
                        const float* __restrict__ out_mt,
                        float* __restrict__ out_W,
                        float* __restrict__ out_commit) {
    int i = blockIdx.x * 256 + threadIdx.x;
    int k = i >> 8;
    float n  = g_nsum;
    float Nn = (out_Nt[k] + EPS_F) * n / (n + (float)KCODES * EPS_F);
    out_W[i] = out_mt[i] / Nn;
    if (i == 0) *out_commit = g_commit / (float)((size_t)NROWS * DDIM);
}

// ---------------- launch ----------------
extern "C" void kernel_launch(void* const* d_in, const int* in_sizes, int n_in,
                              void* d_out, int out_size) {
    const float* ze = (const float*)d_in[0];
    const float* W  = (const float*)d_in[1];
    const float* mt = (const float*)d_in[2];
    const float* Nt = (const float*)d_in[3];
    float* out = (float*)d_out;

    const size_t off_zq     = 0;
    const size_t off_commit = (size_t)NROWS * DDIM;
    const size_t off_idx    = off_commit + 1;
    const size_t off_W      = off_idx + NROWS;
    const size_t off_mt     = off_W + (size_t)KCODES * DDIM;
    const size_t off_Nt     = off_mt + (size_t)KCODES * DDIM;

    k_init<<<(KCODES * DDIM) / 256, 256>>>(W, mt, out + off_mt);

    static int smem_set = 0;
    if (!smem_set) {
        cudaFuncSetAttribute(k_argmin, cudaFuncAttributeMaxDynamicSharedMemorySize,
                             ARG_SMEM);
        smem_set = 1;
    }
    k_argmin<<<148, 256, ARG_SMEM>>>(ze, W);

    k_scatter<<<NROWS / 4, 256>>>(ze, W, out + off_zq, out + off_idx, out + off_mt);
    k_fin_nt<<<KCODES / 256, 256>>>(Nt, out + off_Nt);
    k_fin_w<<<(KCODES * DDIM) / 256, 256>>>(out + off_Nt, out + off_mt,
                                            out + off_W, out + off_commit);
}

// round 6
// speedup vs baseline: 2.1870x; 2.1870x over previous
#include <cuda_runtime.h>
#include <cuda_fp16.h>
#include <cstdint>
#include <cstddef>

#define KCODES 8192
#define DDIM   256
#define NROWS  32768
#define GAMMA_F 0.99f
#define EPS_F   1e-5f

#define KA   768            // 3 fp16 segments * 256
#define NKC  (KA / 32)      // 24 K-chunks of 32
#define LDH  40             // padded halves per smem row (80B)

// ---------------- device scratch ----------------
__device__ __half g_Az[(size_t)NROWS * KA];
__device__ __half g_Bw[(size_t)KCODES * KA];
__device__ unsigned long long g_best[NROWS];
__device__ float g_wnorm[KCODES];
__device__ float g_cnt[KCODES];
__device__ float g_commit;
__device__ float g_nsum;

// ---------------- helpers ----------------
__device__ __forceinline__ uint32_t smem_u32(const void* p) {
    uint32_t a;
    asm("{ .reg .u64 t; cvta.to.shared.u64 t, %1; cvt.u32.u64 %0, t; }" : "=r"(a) : "l"(p));
    return a;
}
__device__ __forceinline__ void cp16(uint32_t s, const void* g) {
    asm volatile("cp.async.cg.shared.global [%0], [%1], 16;" :: "r"(s), "l"(g));
}
#define CP_COMMIT() asm volatile("cp.async.commit_group;" ::: "memory")
#define CP_WAIT(n)  asm volatile("cp.async.wait_group %0;" :: "n"(n) : "memory")

__device__ __forceinline__ void ldsm4(uint32_t* r, uint32_t addr) {
    asm volatile("ldmatrix.sync.aligned.m8n8.x4.shared.b16 {%0,%1,%2,%3}, [%4];"
                 : "=r"(r[0]), "=r"(r[1]), "=r"(r[2]), "=r"(r[3]) : "r"(addr));
}
__device__ __forceinline__ void mma16816(float* c, const uint32_t* a,
                                         uint32_t b0, uint32_t b1) {
    asm volatile(
        "mma.sync.aligned.m16n8k16.row.col.f32.f16.f16.f32 "
        "{%0,%1,%2,%3}, {%4,%5,%6,%7}, {%8,%9}, {%0,%1,%2,%3};"
        : "+f"(c[0]), "+f"(c[1]), "+f"(c[2]), "+f"(c[3])
        : "r"(a[0]), "r"(a[1]), "r"(a[2]), "r"(a[3]), "r"(b0), "r"(b1));
}
__device__ __forceinline__ unsigned long long fkey(float s, int code) {
    unsigned u = __float_as_uint(s);
    u = (u & 0x80000000u) ? ~u : (u | 0x80000000u);
    return ((unsigned long long)u << 32) | (unsigned)(KCODES - 1 - code);
}
__device__ __forceinline__ unsigned long long umax64(unsigned long long a, unsigned long long b) {
    return a > b ? a : b;
}

// ---------------- prep: fp16 2-way split, 3 augmented segments ----------------
// Az = [z0, z1, z0],  Bw = [w0, w0, w1]  ->  z0w0 + z1w0 + z0w1
__global__ void k_prep(const float* __restrict__ ze, const float* __restrict__ W) {
    int i = blockIdx.x * 256 + threadIdx.x;     // covers NROWS*DDIM
    int row = i >> 8, d = i & 255;
    {
        float a = ze[i];
        __half h0 = __float2half_rn(a);
        __half h1 = __float2half_rn(a - __half2float(h0));
        __half* p = g_Az + (size_t)row * KA + d;
        p[0] = h0; p[256] = h1; p[512] = h0;
    }
    if (i < KCODES * DDIM) {
        float w = W[i];
        __half h0 = __float2half_rn(w);
        __half h1 = __float2half_rn(w - __half2float(h0));
        __half* p = g_Bw + (size_t)row * KA + d;
        p[0] = h0; p[256] = h0; p[512] = h1;
    }
}

// ---------------- init ----------------
__global__ void k_init(const float* __restrict__ W, const float* __restrict__ mt,
                       float* __restrict__ out_mt) {
    int i = blockIdx.x * blockDim.x + threadIdx.x;
    out_mt[i] = GAMMA_F * mt[i];
    if (i < KCODES) {
        const float4* w = (const float4*)(W + (size_t)i * DDIM);
        float s = 0.f;
        #pragma unroll 8
        for (int q = 0; q < DDIM / 4; ++q) {
            float4 v = w[q];
            s += v.x * v.x + v.y * v.y + v.z * v.z + v.w * v.w;
        }
        g_wnorm[i] = 0.5f * s;
        g_cnt[i]   = 0.f;
    }
    if (i < NROWS) g_best[i] = 0ull;
    if (i == 0) { g_commit = 0.f; g_nsum = 0.f; }
}

// ---------------- HMMA fused score-GEMM + argmax ----------------
// grid (256 rowtiles, 64 coltiles); CTA tile 128x128; warp grid 4(M)x2(N),
// warp tile 32x64; K-chunk 32, double-buffered cp.async.
__global__ void __launch_bounds__(256, 2) k_argmin_mma() {
    __shared__ __half sA[2][128 * LDH];
    __shared__ __half sB[2][128 * LDH];

    const int tid  = threadIdx.x;
    const int wid  = tid >> 5;
    const int lane = tid & 31;
    const int rowBase = blockIdx.x * 128;
    const int nBase   = blockIdx.y * 128;

    const int lr = tid >> 2;        // loader row 0..63 (x2)
    const int lc = tid & 3;         // 16B chunk 0..3
    uint32_t aS[2], bS[2];
    #pragma unroll
    for (int b = 0; b < 2; ++b) {
        aS[b] = smem_u32(&sA[b][0]);
        bS[b] = smem_u32(&sB[b][0]);
    }

    float acc[2][8][4];
    #pragma unroll
    for (int i = 0; i < 2; ++i)
        #pragma unroll
        for (int j = 0; j < 8; ++j)
            #pragma unroll
            for (int q = 0; q < 4; ++q) acc[i][j][q] = 0.f;

    // ---- issue chunk 0 ----
    {
        #pragma unroll
        for (int p = 0; p < 2; ++p) {
            int r = lr + 64 * p;
            cp16(aS[0] + r * (LDH * 2) + lc * 16,
                 g_Az + (size_t)(rowBase + r) * KA + lc * 8);
            cp16(bS[0] + r * (LDH * 2) + lc * 16,
                 g_Bw + (size_t)(nBase + r) * KA + lc * 8);
        }
        CP_COMMIT();
    }

    const int mOff = (wid >> 1) * 32;
    const int nOff = (wid & 1) * 64;
    const int lmRow = lane & 15;
    const int lmCol = (lane >> 4) * 16;

    for (int kc = 0; kc < NKC; ++kc) {
        const int buf = kc & 1;
        if (kc + 1 < NKC) {
            const int nb = buf ^ 1;
            const int ko = (kc + 1) * 32;
            #pragma unroll
            for (int p = 0; p < 2; ++p) {
                int r = lr + 64 * p;
                cp16(aS[nb] + r * (LDH * 2) + lc * 16,
                     g_Az + (size_t)(rowBase + r) * KA + ko + lc * 8);
                cp16(bS[nb] + r * (LDH * 2) + lc * 16,
                     g_Bw + (size_t)(nBase + r) * KA + ko + lc * 8);
            }
            CP_COMMIT();
            CP_WAIT(1);
        } else {
            CP_WAIT(0);
        }
        __syncthreads();

        #pragma unroll
        for (int k16 = 0; k16 < 2; ++k16) {
            const int kb = k16 * 32 + lmCol;   // byte offset along row
            uint32_t af[2][4];
            #pragma unroll
            for (int i = 0; i < 2; ++i)
                ldsm4(af[i], aS[buf] + (mOff + i * 16 + lmRow) * (LDH * 2) + kb);
            uint32_t bf[4][4];
            #pragma unroll
            for (int g = 0; g < 4; ++g)
                ldsm4(bf[g], bS[buf] + (nOff + g * 16 + lmRow) * (LDH * 2) + kb);
            #pragma unroll
            for (int i = 0; i < 2; ++i)
                #pragma unroll
                for (int j = 0; j < 8; ++j) {
                    const int g = j >> 1, h = j & 1;
                    mma16816(acc[i][j], af[i], bf[g][h], bf[g][h + 2]);
                }
        }
        __syncthreads();   // protect buf before next-iteration cp.async overwrite
    }

    // ---- epilogue: packed-key argmax ----
    #pragma unroll
    for (int i = 0; i < 2; ++i)
        #pragma unroll
        for (int h = 0; h < 2; ++h) {
            const int row = rowBase + mOff + i * 16 + (lane >> 2) + h * 8;
            unsigned long long key = 0ull;
            #pragma unroll
            for (int j = 0; j < 8; ++j) {
                const int col = nBase + nOff + j * 8 + (lane & 3) * 2;
                float s0 = acc[i][j][h * 2]     - __ldg(&g_wnorm[col]);
                float s1 = acc[i][j][h * 2 + 1] - __ldg(&g_wnorm[col + 1]);
                key = umax64(key, fkey(s0, col));
                key = umax64(key, fkey(s1, col + 1));
            }
            key = umax64(key, __shfl_xor_sync(0xffffffffu, key, 1));
            key = umax64(key, __shfl_xor_sync(0xffffffffu, key, 2));
            if ((lane & 3) == 0) atomicMax(&g_best[row], key);
        }
}

// ---------------- gather/scatter ----------------
__global__ void k_scatter(const float* __restrict__ ze, const float* __restrict__ W,
                          float* __restrict__ out_zq, float* __restrict__ out_idx,
                          float* __restrict__ out_mt) {
    const int tid  = threadIdx.x;
    const int row  = blockIdx.x * 4 + (tid >> 6);
    const int lane = tid & 63;
    const int idx  = KCODES - 1 - (int)(g_best[row] & 0xffffffffu);

    const float4 z = *(const float4*)(ze + (size_t)row * DDIM + lane * 4);
    const float4 w = *(const float4*)(W  + (size_t)idx * DDIM + lane * 4);

    float4 q;
    q.x = z.x + (w.x - z.x);
    q.y = z.y + (w.y - z.y);
    q.z = z.z + (w.z - z.z);
    q.w = z.w + (w.w - z.w);
    *(float4*)(out_zq + (size_t)row * DDIM + lane * 4) = q;

    float dx = w.x - z.x, dy = w.y - z.y, dz = w.z - z.z, dw = w.w - z.w;
    float csum = dx * dx + dy * dy + dz * dz + dw * dw;

    const float s = 1.0f - GAMMA_F;
    float* mptr = out_mt + (size_t)idx * DDIM + lane * 4;
    atomicAdd(mptr + 0, s * z.x);
    atomicAdd(mptr + 1, s * z.y);
    atomicAdd(mptr + 2, s * z.z);
    atomicAdd(mptr + 3, s * z.w);

    if (lane == 0) {
        atomicAdd(&g_cnt[idx], 1.0f);
        out_idx[row] = (float)idx;
    }

    __shared__ float red[8];
    #pragma unroll
    for (int off = 16; off > 0; off >>= 1)
        csum += __shfl_down_sync(0xffffffffu, csum, off);
    if ((tid & 31) == 0) red[tid >> 5] = csum;
    __syncthreads();
    if (tid < 8) {
        float v = red[tid];
        #pragma unroll
        for (int off = 4; off > 0; off >>= 1)
            v += __shfl_down_sync(0xffu, v, off);
        if (tid == 0) atomicAdd(&g_commit, v);
    }
}

// ---------------- Nt_new + n ----------------
__global__ void k_fin_nt(const float* __restrict__ Nt, float* __restrict__ out_Nt) {
    int k = blockIdx.x * 256 + threadIdx.x;
    float v = GAMMA_F * Nt[k] + (1.0f - GAMMA_F) * g_cnt[k];
    out_Nt[k] = v;
    __shared__ float red[8];
    float s = v;
    #pragma unroll
    for (int off = 16; off > 0; off >>= 1)
        s += __shfl_down_sync(0xffffffffu, s, off);
    if ((threadIdx.x & 31) == 0) red[threadIdx.x >> 5] = s;
    __syncthreads();
    if (threadIdx.x < 8) {
        float t = red[threadIdx.x];
        #pragma unroll
        for (int off = 4; off > 0; off >>= 1)
            t += __shfl_down_sync(0xffu, t, off);
        if (threadIdx.x == 0) atomicAdd(&g_nsum, t);
    }
}

// ---------------- embedW_new + commit ----------------
__global__ void k_fin_w(const float* __restrict__ out_Nt,
                        const float* __restrict__ out_mt,
                        float* __restrict__ out_W,
                        float* __restrict__ out_commit) {
    int i = blockIdx.x * 256 + threadIdx.x;
    int k = i >> 8;
    float n  = g_nsum;
    float Nn = (out_Nt[k] + EPS_F) * n / (n + (float)KCODES * EPS_F);
    out_W[i] = out_mt[i] / Nn;
    if (i == 0) *out_commit = g_commit / (float)((size_t)NROWS * DDIM);
}

// ---------------- launch ----------------
extern "C" void kernel_launch(void* const* d_in, const int* in_sizes, int n_in,
                              void* d_out, int out_size) {
    const float* ze = (const float*)d_in[0];
    const float* W  = (const float*)d_in[1];
    const float* mt = (const float*)d_in[2];
    const float* Nt = (const float*)d_in[3];
    float* out = (float*)d_out;

    const size_t off_zq     = 0;
    const size_t off_commit = (size_t)NROWS * DDIM;
    const size_t off_idx    = off_commit + 1;
    const size_t off_W      = off_idx + NROWS;
    const size_t off_mt     = off_W + (size_t)KCODES * DDIM;
    const size_t off_Nt     = off_mt + (size_t)KCODES * DDIM;

    k_prep<<<(NROWS * DDIM) / 256, 256>>>(ze, W);
    k_init<<<(KCODES * DDIM) / 256, 256>>>(W, mt, out + off_mt);

    dim3 grid(NROWS / 128, KCODES / 128);   // x = rowtile (fast) -> B coltile L2-hot
    k_argmin_mma<<<grid, 256>>>();

    k_scatter<<<NROWS / 4, 256>>>(ze, W, out + off_zq, out + off_idx, out + off_mt);
    k_fin_nt<<<KCODES / 256, 256>>>(Nt, out + off_Nt);
    k_fin_w<<<(KCODES * DDIM) / 256, 256>>>(out + off_Nt, out + off_mt,
                                            out + off_W, out + off_commit);
}